// round 8
// baseline (speedup 1.0000x reference)
#include <cuda_runtime.h>
#include <math.h>
#include <stdint.h>

#define T_LEN   8192
#define F_DIM   8
#define B_SZ    128
#define NLAGS   24
#define THREADS 256
#define NWARPS  (THREADS / 32)      // 8
#define CHUNK   (T_LEN / THREADS)   // 32
#define WIN     (CHUNK + NLAGS)     // 56-element register window
#define NCH     8                   // chunks per row
#define CELEM   (T_LEN / NCH)       // 1024 elements / chunk
#define CBYTES  (CELEM * F_DIM * 4) // 32768 bytes / chunk
#define DYN_SMEM ((2 * CELEM * F_DIM + T_LEN + (T_LEN >> 5)) * 4)  // 2 bufs + padded zs

__device__ float g_partials[B_SZ];
__device__ int   g_count = 0;

__device__ __forceinline__ int zi(int t) { return t + (t >> 5); }

__device__ __forceinline__ uint32_t s2u(const void* p) {
    return (uint32_t)__cvta_generic_to_shared(p);
}
__device__ __forceinline__ void mbar_init(uint32_t a, uint32_t cnt) {
    asm volatile("mbarrier.init.shared.b64 [%0], %1;" :: "r"(a), "r"(cnt) : "memory");
}
__device__ __forceinline__ void mbar_expect_tx(uint32_t a, uint32_t bytes) {
    asm volatile("mbarrier.arrive.expect_tx.shared.b64 _, [%0], %1;" :: "r"(a), "r"(bytes) : "memory");
}
__device__ __forceinline__ void bulk_g2s(uint32_t dst, const void* src, uint32_t bytes, uint32_t mbar) {
    asm volatile("cp.async.bulk.shared::cta.global.mbarrier::complete_tx::bytes [%0], [%1], %2, [%3];"
                 :: "r"(dst), "l"(src), "r"(bytes), "r"(mbar) : "memory");
}
__device__ __forceinline__ void mbar_wait(uint32_t a, uint32_t ph) {
    asm volatile(
        "{\n\t.reg .pred P;\n\t"
        "WL_%=:\n\t"
        "mbarrier.try_wait.parity.acquire.cta.shared::cta.b64 P, [%0], %1, 0x989680;\n\t"
        "@P bra.uni WD_%=;\n\t"
        "bra.uni WL_%=;\n\t"
        "WD_%=:\n\t}"
        :: "r"(a), "r"(ph) : "memory");
}

__global__ __launch_bounds__(THREADS)
void autocorr_kernel(const float* __restrict__ input,
                     const float* __restrict__ lagw,
                     const float* __restrict__ seas,
                     float* __restrict__ out) {
    extern __shared__ float dyn[];
    float* buf = dyn;                        // [2][CELEM*F_DIM] raw chunks (64 KB)
    float* zs  = dyn + 2 * CELEM * F_DIM;    // padded f0 column (33 KB)

    __shared__ float red[2 * NWARPS];
    __shared__ float warp_sxy[NWARPS][NLAGS];
    __shared__ alignas(16) uint64_t mb[2];

    const int b    = blockIdx.x;
    const int tid  = threadIdx.x;
    const int warp = tid >> 5;
    const int lane = tid & 31;
    const char* rowb = (const char*)(input + (size_t)b * T_LEN * F_DIM);

    const uint32_t mbar0 = s2u(&mb[0]);
    const uint32_t mbar1 = s2u(&mb[1]);
    const uint32_t bufu  = s2u(buf);

    if (tid == 0) {
        mbar_init(mbar0, 1);
        mbar_init(mbar1, 1);
        asm volatile("fence.proxy.async.shared::cta;" ::: "memory");
    }
    __syncthreads();

    // ---- bulk-copy pipeline: stream 8x32KB contiguous chunks, extract f0 ----
    int ph0 = 0, ph1 = 0;
    if (tid == 0) {   // prologue: chunk 0 -> buf0
        mbar_expect_tx(mbar0, CBYTES);
        bulk_g2s(bufu, rowb, CBYTES, mbar0);
    }

    float lsum = 0.f, lsq = 0.f;
    #pragma unroll
    for (int c = 0; c < NCH; c++) {
        const int cur = c & 1;
        if (tid == 0 && c + 1 < NCH) {   // issue next chunk into the other buffer
            uint32_t m = (cur ? mbar0 : mbar1);
            mbar_expect_tx(m, CBYTES);
            bulk_g2s(bufu + (cur ^ 1) * CBYTES, rowb + (size_t)(c + 1) * CBYTES, CBYTES, m);
        }
        // wait current chunk
        if (cur) { mbar_wait(mbar1, ph1); ph1 ^= 1; }
        else     { mbar_wait(mbar0, ph0); ph0 ^= 1; }

        // extract f0 (stride-8 floats) into zs; sums on the fly
        const float* bc = buf + cur * CELEM * F_DIM;
        #pragma unroll
        for (int k = 0; k < CELEM / THREADS; k++) {
            int e = tid + k * THREADS;
            float v = bc[e * F_DIM];
            zs[zi(c * CELEM + e)] = v;
            lsum += v;
            lsq  += v * v;
        }
        __syncthreads();   // buffer fully consumed before it can be reissued
    }

    #pragma unroll
    for (int o = 16; o > 0; o >>= 1) {
        lsum += __shfl_xor_sync(0xffffffffu, lsum, o);
        lsq  += __shfl_xor_sync(0xffffffffu, lsq,  o);
    }
    if (lane == 0) { red[warp] = lsum; red[NWARPS + warp] = lsq; }
    __syncthreads();

    // ---- cross-products from a 56-elem register window (raw data:
    //      Pearson per window is invariant to the global normalization) ----
    float w[WIN];
    const int i0 = tid * CHUNK;
    #pragma unroll
    for (int j = 0; j < WIN; j++) {
        int idx = i0 + j;
        w[j] = (idx < T_LEN) ? zs[zi(idx)] : 0.f;
    }
    float acc[NLAGS];
    #pragma unroll
    for (int l = 0; l < NLAGS; l++) acc[l] = 0.f;
    #pragma unroll
    for (int j = 0; j < CHUNK; j++) {
        #pragma unroll
        for (int l = 0; l < NLAGS; l++)
            acc[l] = fmaf(w[j], w[j + l + 1], acc[l]);
    }

    #pragma unroll
    for (int l = 0; l < NLAGS; l++) {
        float v = acc[l];
        #pragma unroll
        for (int o = 16; o > 0; o >>= 1)
            v += __shfl_xor_sync(0xffffffffu, v, o);
        if (lane == 0) warp_sxy[warp][l] = v;
    }
    __syncthreads();

    // ---- epilogue: one warp finishes the whole row ----
    if (warp == 0) {
        float e = (lane < NLAGS) ? __expf(__ldg(lagw + lane)) : 0.f;
        float se = e;
        #pragma unroll
        for (int o = 16; o > 0; o >>= 1) se += __shfl_xor_sync(0xffffffffu, se, o);
        float coef = e / se;
        if (lane == 11) coef += __ldg(seas + 0);   // lag 12
        if (lane == 23) coef += __ldg(seas + 1);   // lag 24

        float val = 0.f;
        if (lane < NLAGS) {
            const int l   = lane;
            const int lag = l + 1;
            float sxy = 0.f;
            #pragma unroll
            for (int wi = 0; wi < NWARPS; wi++) sxy += warp_sxy[wi][l];

            float S = 0.f, Q = 0.f;
            #pragma unroll
            for (int i = 0; i < NWARPS; i++) { S += red[i]; Q += red[NWARPS + i]; }

            float hs = 0.f, hq = 0.f, ts = 0.f, tq = 0.f;
            for (int t = 0; t < lag; t++)            { float v = zs[zi(t)]; hs += v; hq += v * v; }
            for (int t = T_LEN - lag; t < T_LEN; t++){ float v = zs[zi(t)]; ts += v; tq += v * v; }

            const float Sx  = S - ts,  Sy  = S - hs;
            const float Sxx = Q - tq,  Syy = Q - hq;
            const float n   = (float)(T_LEN - lag);

            float num = sxy - Sx * Sy / n;
            float vx  = Sxx - Sx * Sx / n;
            float vy  = Syy - Sy * Sy / n;
            float r   = num / (sqrtf(fmaxf(vx, 0.f)) * sqrtf(fmaxf(vy, 0.f)));
            r = fminf(1.f, fmaxf(-1.f, r));
            val = r * coef;
        }
        #pragma unroll
        for (int o = 16; o > 0; o >>= 1) val += __shfl_xor_sync(0xffffffffu, val, o);

        int ticket = 0;
        if (lane == 0) {
            g_partials[b] = val;
            __threadfence();
            ticket = atomicAdd(&g_count, 1);
        }
        ticket = __shfl_sync(0xffffffffu, ticket, 0);

        if (ticket == B_SZ - 1) {   // last block folds the 128 row partials
            __threadfence();
            float s = g_partials[lane] + g_partials[lane + 32]
                    + g_partials[lane + 64] + g_partials[lane + 96];
            #pragma unroll
            for (int o = 16; o > 0; o >>= 1) s += __shfl_xor_sync(0xffffffffu, s, o);
            if (lane == 0) {
                out[0] = s * (1.f / (float)B_SZ);
                g_count = 0;   // reset for next graph replay
            }
        }
    }
}

extern "C" void kernel_launch(void* const* d_in, const int* in_sizes, int n_in,
                              void* d_out, int out_size) {
    const float* input = (const float*)d_in[0];   // input_sequence (128,8192,8)
    // d_in[1] = hidden_states — never referenced by the math; intentionally unused
    const float* lagw  = (const float*)d_in[2];   // lag_weights (24,)
    const float* seas  = (const float*)d_in[3];   // seasonal_importance (2,)
    float* out = (float*)d_out;

    cudaFuncSetAttribute(autocorr_kernel,
                         cudaFuncAttributeMaxDynamicSharedMemorySize, DYN_SMEM);
    autocorr_kernel<<<B_SZ, THREADS, DYN_SMEM>>>(input, lagw, seas, out);
}